// round 1
// baseline (speedup 1.0000x reference)
#include <cuda_runtime.h>

#define THREADS 256
#define NW 8        // warps per block
// 4096 paths total (2048 x-set + 2048 y-set), one warp per path -> 512 blocks

// Level offsets in the 780-dim signature (levels 1..4 of d=5):
// L1: [0,5)  L2: [5,30)  L3: [30,155)  L4: [155,780)
__device__ double g_acc[2][784];   // [set][component], padded

struct WarpScratch {
    float dxs[640];   // 127 steps * 5 channels (increments, sigma-scaled)
    float a1[8];      // A1 = S1 + dx/4
    float c1[8];      // C1 = S1 + dx/3
    float d1[8];      // D1 = S1 + dx/2
    float a2[32];     // A2 = S2 + A1 (x) dx / 3
    float b2[32];     // B2 = S2 + C1 (x) dx / 2
};

__global__ void zero_acc_kernel() {
    int i = blockIdx.x * blockDim.x + threadIdx.x;
    if (i < 2 * 784) ((double*)g_acc)[i] = 0.0;
}

// 4-SEL pick of dx[c] from registers (predicates on loop-invariant c get hoisted)
__device__ __forceinline__ float sel5(int c, float d0, float d1, float d2,
                                      float d3, float d4) {
    float r = d4;
    r = (c == 3) ? d3 : r;
    r = (c == 2) ? d2 : r;
    r = (c == 1) ? d1 : r;
    r = (c == 0) ? d0 : r;
    return r;
}

__global__ void __launch_bounds__(THREADS) sig_kernel(
    const float* __restrict__ xin,
    const float* __restrict__ yin,
    const float* __restrict__ sigma)
{
    __shared__ WarpScratch ws[NW];
    __shared__ float shacc[784];

    const int lane = threadIdx.x & 31;
    const int wib  = threadIdx.x >> 5;
    const int gw   = blockIdx.x * NW + wib;   // global warp id = path id, 0..4095
    const int set  = gw >> 11;                // 0: x (scaled by sigma), 1: y
    const int bidx = gw & 2047;

    // zero the block-level accumulator (all warps in a block share one set,
    // since 2048 % NW == 0 the set is uniform per block)
    for (int i = threadIdx.x; i < 784; i += THREADS) shacc[i] = 0.0f;
    __syncthreads();

    WarpScratch& W = ws[wib];
    const float* path = (set == 0 ? xin : yin) + (size_t)bidx * 640;

    const float sc1 = (set == 0) ? sigma[0] : 1.0f;
    const float sc2 = (set == 0) ? sigma[1] : 1.0f;
    const float sc3 = (set == 0) ? sigma[2] : 1.0f;
    const float sc4 = (set == 0) ? sigma[3] : 1.0f;

    // stage sigma-scaled increments into shared (coalesced global reads)
    for (int i = lane; i < 635; i += 32) {
        int c = i % 5;
        float s = sel5(c, 1.0f, sc1, sc2, sc3, sc4);
        W.dxs[i] = (path[i + 5] - path[i]) * s;
    }
    __syncwarp();

    // --- per-lane ownership ---------------------------------------------
    // lane < 5  : owns S1[lane]
    // lane < 25 : owns S2[lane]  (index ab = 5a+b)
    // lane l    : owns S3[4l+i], i<4 (valid if 4l+i<125)
    //             owns S4[20l + 5i + e] = A3[4l+i] (x) dx[e]  -> pure register FMA
    int ab3[4], c3[4];
    bool v3[4];
#pragma unroll
    for (int i = 0; i < 4; ++i) {
        int idx = 4 * lane + i;
        v3[i] = (idx < 125);
        int id = v3[i] ? idx : 124;
        ab3[i] = id / 5;
        c3[i]  = id % 5;
    }
    const int abL = ab3[0];
    const int abH = ab3[3];          // abL or abL+1 (<= 2 distinct A2/B2 per lane)
    bool hiF[4];
#pragma unroll
    for (int i = 0; i < 4; ++i) hiF[i] = (ab3[i] != abL);

    const int la = lane / 5;         // for the S2 phase (lane < 25)
    const int lb = lane - 5 * la;

    float s1 = 0.0f, s2 = 0.0f;
    float s3[4] = {0.0f, 0.0f, 0.0f, 0.0f};
    float s4[20];
#pragma unroll
    for (int j = 0; j < 20; ++j) s4[j] = 0.0f;

    int off = 0;
    for (int t = 0; t < 127; ++t, off += 5) {
        const float d0 = W.dxs[off + 0];
        const float d1 = W.dxs[off + 1];
        const float d2 = W.dxs[off + 2];
        const float d3 = W.dxs[off + 3];
        const float d4 = W.dxs[off + 4];

        // phase 1: level-1 helpers (old S1)
        if (lane < 5) {
            float dl = sel5(lane, d0, d1, d2, d3, d4);
            W.a1[lane] = fmaf(dl, 0.25f,        s1);
            W.c1[lane] = fmaf(dl, (1.0f/3.0f),  s1);
            W.d1[lane] = fmaf(dl, 0.5f,         s1);
            s1 += dl;
        }
        __syncwarp();

        // phase 2: level-2 helpers + S2 update (old S2)
        if (lane < 25) {
            float dxb = sel5(lb, d0, d1, d2, d3, d4);
            float a2v = fmaf(W.a1[la] * (1.0f/3.0f), dxb, s2);
            float b2v = fmaf(W.c1[la] * 0.5f,        dxb, s2);
            s2 = fmaf(W.d1[la], dxb, s2);
            W.a2[lane] = a2v;
            W.b2[lane] = b2v;
        }
        __syncwarp();

        // phase 3: A3 + S3 update (old S3), then S4 += A3 (x) dx (registers only)
        const float a2L = W.a2[abL], a2H = W.a2[abH];
        const float b2L = W.b2[abL], b2H = W.b2[abH];
        float a3[4];
#pragma unroll
        for (int i = 0; i < 4; ++i) {
            float dxc = sel5(c3[i], d0, d1, d2, d3, d4);
            float A2 = hiF[i] ? a2H : a2L;
            float B2 = hiF[i] ? b2H : b2L;
            float a3v = fmaf(A2 * 0.5f, dxc, s3[i]);
            float s3v = fmaf(B2,        dxc, s3[i]);
            a3[i] = v3[i] ? a3v : 0.0f;
            s3[i] = v3[i] ? s3v : 0.0f;
        }
#pragma unroll
        for (int i = 0; i < 4; ++i) {
            s4[5*i+0] = fmaf(a3[i], d0, s4[5*i+0]);
            s4[5*i+1] = fmaf(a3[i], d1, s4[5*i+1]);
            s4[5*i+2] = fmaf(a3[i], d2, s4[5*i+2]);
            s4[5*i+3] = fmaf(a3[i], d3, s4[5*i+3]);
            s4[5*i+4] = fmaf(a3[i], d4, s4[5*i+4]);
        }
    }

    // --- block reduction: shared float atomics (distinct addrs within warp) ---
    if (lane < 5)  atomicAdd(&shacc[lane], s1);
    if (lane < 25) atomicAdd(&shacc[5 + lane], s2);
#pragma unroll
    for (int i = 0; i < 4; ++i)
        if (v3[i]) atomicAdd(&shacc[30 + 4*lane + i], s3[i]);
#pragma unroll
    for (int i = 0; i < 4; ++i) {
        if (v3[i]) {
#pragma unroll
            for (int e = 0; e < 5; ++e)
                atomicAdd(&shacc[155 + 20*lane + 5*i + e], s4[5*i + e]);
        }
    }
    __syncthreads();

    // --- global: double atomics, 512 contributions per address ---
    for (int i = threadIdx.x; i < 780; i += THREADS)
        atomicAdd(&g_acc[set][i], (double)shacc[i]);
}

__global__ void finalize_kernel(float* out) {
    __shared__ double red[256];
    double s = 0.0;
    for (int e = threadIdx.x; e < 780; e += 256) {
        double d = (g_acc[0][e] - g_acc[1][e]) * (1.0 / 2048.0);
        s += d * d;
    }
    red[threadIdx.x] = s;
    __syncthreads();
    for (int k = 128; k > 0; k >>= 1) {
        if (threadIdx.x < k) red[threadIdx.x] += red[threadIdx.x + k];
        __syncthreads();
    }
    if (threadIdx.x == 0) out[0] = (float)red[0];
}

extern "C" void kernel_launch(void* const* d_in, const int* in_sizes, int n_in,
                              void* d_out, int out_size) {
    (void)in_sizes; (void)n_in; (void)out_size;
    const float* x     = (const float*)d_in[0];
    const float* y     = (const float*)d_in[1];
    const float* sigma = (const float*)d_in[2];
    float* out = (float*)d_out;

    zero_acc_kernel<<<2, 784>>>();          // g_acc persists across graph replays
    sig_kernel<<<512, THREADS>>>(x, y, sigma);
    finalize_kernel<<<1, 256>>>(out);
}

// round 2
// speedup vs baseline: 2.0975x; 2.0975x over previous
#include <cuda_runtime.h>

#define THREADS 128
#define NW 4          // warps per block, one warp per path
#define NBLOCKS 1024  // 4096 paths total

// Signature level offsets (d=5, depth 4): L1 [0,5) L2 [5,30) L3 [30,155) L4 [155,780)
__device__ double g_acc[2][784];

typedef unsigned long long ull;

__device__ __forceinline__ ull pk2(float lo, float hi) {
    ull r; asm("mov.b64 %0, {%1,%2};" : "=l"(r) : "f"(lo), "f"(hi)); return r;
}
__device__ __forceinline__ void unpk2(ull v, float& a, float& b) {
    asm("mov.b64 {%0,%1}, %2;" : "=f"(a), "=f"(b) : "l"(v));
}
__device__ __forceinline__ ull fma2v(ull a, ull b, ull c) {
    ull d; asm("fma.rn.f32x2 %0, %1, %2, %3;" : "=l"(d) : "l"(a), "l"(b), "l"(c));
    return d;
}

__global__ void __launch_bounds__(THREADS, 7) sig_kernel(
    const float* __restrict__ xin,
    const float* __restrict__ yin,
    const float* __restrict__ sigma)
{
    // per-warp increment buffer, stride 8 floats per step (32B-aligned pairs)
    __shared__ float dxs[NW][8 * 127 + 8];
    __shared__ float shacc[784];

    const int lane = threadIdx.x & 31;
    const int wib  = threadIdx.x >> 5;
    const int gw   = blockIdx.x * NW + wib;  // path id 0..4095
    const int set  = gw >> 11;               // 0: x (sigma-scaled), 1: y
    const int bidx = gw & 2047;

    for (int i = threadIdx.x; i < 784; i += THREADS) shacc[i] = 0.0f;
    __syncthreads();

    float* dx = dxs[wib];
    const float* path = (set == 0 ? xin : yin) + (size_t)bidx * 640;

    const float sc1 = (set == 0) ? sigma[0] : 1.0f;
    const float sc2 = (set == 0) ? sigma[1] : 1.0f;
    const float sc3 = (set == 0) ? sigma[2] : 1.0f;
    const float sc4 = (set == 0) ? sigma[3] : 1.0f;

    // stage sigma-scaled increments (coalesced global reads)
    for (int i = lane; i < 635; i += 32) {
        int t = i / 5;
        int c = i - 5 * t;
        float s = (c == 0) ? 1.0f : (c == 1) ? sc1 : (c == 2) ? sc2
                : (c == 3) ? sc3 : sc4;
        dx[8 * t + c] = (path[i + 5] - path[i]) * s;
    }
    __syncwarp();

    // --- lane ownership (all loop-invariant) ------------------------------
    // lanes 0-4  own S1[lane]; lanes 0-24 own S2[5a+b]
    // lane l owns S3[4l+i] (i<4, valid while 4l+i<125) and S4[20l+5i+e]
    const int lane5 = (lane < 4) ? lane : 4;
    const int lc    = (lane < 24) ? lane : 24;
    const int la    = lc / 5;
    const int lb    = lc - 5 * la;

    int ab3[4], c3[4];
    bool v3[4];
#pragma unroll
    for (int i = 0; i < 4; ++i) {
        int idx = 4 * lane + i;
        v3[i] = (idx < 125);
        int id = v3[i] ? idx : 124;   // clamp: lane 31 dups comp 124 (finite, masked later)
        ab3[i] = id / 5;
        c3[i]  = id - 5 * ab3[i];
    }

    float s1 = 0.0f, s2 = 0.0f;
    float s3v[4] = {0.0f, 0.0f, 0.0f, 0.0f};
    float s4e[4] = {0.0f, 0.0f, 0.0f, 0.0f};
    ull s4p[8];
#pragma unroll
    for (int j = 0; j < 8; ++j) s4p[j] = 0ULL;

    for (int t = 0; t < 127; ++t) {
        const float* dxt = dx + 8 * t;
        const ull d01 = *reinterpret_cast<const ull*>(dxt);      // (d0,d1) packed
        const ull d23 = *reinterpret_cast<const ull*>(dxt + 2);  // (d2,d3) packed
        const float d4s = dxt[4];

        // phase 1: level-1 helpers (lanes>=5 compute harmless clones of lane4)
        const float dl = dxt[lane5];
        const float a1 = fmaf(dl, 0.25f,        s1);
        const float c1 = fmaf(dl, (1.0f/3.0f),  s1);
        const float d1 = fmaf(dl, 0.5f,         s1);
        s1 += dl;
        const float a1g = __shfl_sync(0xffffffffu, a1, la);
        const float c1g = __shfl_sync(0xffffffffu, c1, la);
        const float d1g = __shfl_sync(0xffffffffu, d1, la);

        // phase 2: level-2 helpers + S2 update
        const float dxb = dxt[lb];
        const float a2  = fmaf(a1g * (1.0f/3.0f), dxb, s2);
        const float b2  = fmaf(c1g * 0.5f,        dxb, s2);
        s2 = fmaf(d1g, dxb, s2);
        const float a2h = 0.5f * a2;   // pre-halve once; phase 3 uses it 4x

        // phase 3: A3 + S3 update, S4 += A3 (x) dx (register FFMA2)
#pragma unroll
        for (int i = 0; i < 4; ++i) {
            const float A2h = __shfl_sync(0xffffffffu, a2h, ab3[i]);
            const float B2  = __shfl_sync(0xffffffffu, b2,  ab3[i]);
            const float dxc = dxt[c3[i]];
            const float a3  = fmaf(A2h, dxc, s3v[i]);
            s3v[i] = fmaf(B2, dxc, s3v[i]);
            const ull a3d = pk2(a3, a3);
            s4p[2*i]     = fma2v(a3d, d01, s4p[2*i]);
            s4p[2*i + 1] = fma2v(a3d, d23, s4p[2*i + 1]);
            s4e[i] = fmaf(a3, d4s, s4e[i]);
        }
    }

    // --- block reduction: shared float atomics ----------------------------
    if (lane < 5)  atomicAdd(&shacc[lane], s1);
    if (lane < 25) atomicAdd(&shacc[5 + lane], s2);
#pragma unroll
    for (int i = 0; i < 4; ++i)
        if (v3[i]) atomicAdd(&shacc[30 + 4*lane + i], s3v[i]);
#pragma unroll
    for (int i = 0; i < 4; ++i) {
        if (v3[i]) {
            float e0, e1, e2, e3;
            unpk2(s4p[2*i],     e0, e1);
            unpk2(s4p[2*i + 1], e2, e3);
            const int base = 155 + 20*lane + 5*i;
            atomicAdd(&shacc[base + 0], e0);
            atomicAdd(&shacc[base + 1], e1);
            atomicAdd(&shacc[base + 2], e2);
            atomicAdd(&shacc[base + 3], e3);
            atomicAdd(&shacc[base + 4], s4e[i]);
        }
    }
    __syncthreads();

    // global: double atomics, 1024 contributions per address (spread over 780)
    for (int i = threadIdx.x; i < 780; i += THREADS)
        atomicAdd(&g_acc[set][i], (double)shacc[i]);
}

// reads g_acc, writes result, then zeroes g_acc for the next graph replay
__global__ void finalize_kernel(float* out) {
    __shared__ double red[256];
    double s = 0.0;
    for (int e = threadIdx.x; e < 780; e += 256) {
        double d = (g_acc[0][e] - g_acc[1][e]) * (1.0 / 2048.0);
        s += d * d;
    }
    red[threadIdx.x] = s;
    __syncthreads();
    for (int k = 128; k > 0; k >>= 1) {
        if (threadIdx.x < k) red[threadIdx.x] += red[threadIdx.x + k];
        __syncthreads();
    }
    if (threadIdx.x == 0) out[0] = (float)red[0];
    // reset accumulators (reads all completed before the first __syncthreads)
    for (int e = threadIdx.x; e < 2 * 784; e += 256)
        ((double*)g_acc)[e] = 0.0;
}

extern "C" void kernel_launch(void* const* d_in, const int* in_sizes, int n_in,
                              void* d_out, int out_size) {
    (void)in_sizes; (void)n_in; (void)out_size;
    const float* x     = (const float*)d_in[0];
    const float* y     = (const float*)d_in[1];
    const float* sigma = (const float*)d_in[2];
    float* out = (float*)d_out;

    sig_kernel<<<NBLOCKS, THREADS>>>(x, y, sigma);
    finalize_kernel<<<1, 256>>>(out);
}